// round 6
// baseline (speedup 1.0000x reference)
#include <cuda_runtime.h>

// Problem constants (fixed shapes)
#define BATCH   2
#define H       64
#define W       64
#define C       128
#define N_IN    (H * W * C)            // 524288
#define N_POOL  ((H/2) * (W/2) * C)    // 131072
#define N_OUT   32

// Output layout (concatenated, all float32):
//   [0, OFF1)       w_zero #1 : 33,554,432
//   [OFF1, OFF2)    b_out_u_  : 64
//   [OFF2, OFF3)    w_zero #2 : 33,554,432
//   [OFF3, TOTAL)   b_out_l_  : 64
#define OFF1    (BATCH * N_IN * N_OUT)         // 33554432
#define OFF2    (OFF1 + BATCH * N_OUT)         // 33554496
#define OFF3    (OFF2 + BATCH * N_IN * N_OUT)  // 67108928
#define TOTAL   (OFF3 + BATCH * N_OUT)         // 67108992
#define TOTAL4  (TOTAL / 4)                    // 16777248 float4s

#define NTHREADS 256
#define ZGRID    1184                          // 148 SMs x 8: one wave
#define PGRID    512
#define RGRID    1024                          // 512 blocks per batch
#define ROWS_TOTAL (BATCH * N_POOL)            // 262144
#define QPB      (N_POOL * 8)                  // quads per batch per tensor = 1048576
#define RSTRIDE  ((RGRID / 2) * NTHREADS)      // 131072 -> exactly 8 iters/thread

// Pooled interval bounds, written by pool_kernel, read by reduce_kernel.
// 2 x 1 MB -> L2-resident. Fully overwritten every call (deterministic).
__device__ float g_bu[ROWS_TOTAL];
__device__ float g_bl[ROWS_TOTAL];

// ---------------------------------------------------------------------------
// Phase 1: pure write stream, branch-free. Zeros the ENTIRE output including
// the bias slots (pool_kernel re-seeds them afterward).
// ---------------------------------------------------------------------------
__global__ void __launch_bounds__(NTHREADS)
zero_kernel(float* __restrict__ out) {
    float4* o4 = reinterpret_cast<float4*>(out);
    const float4 z = make_float4(0.f, 0.f, 0.f, 0.f);
    const int stride = ZGRID * NTHREADS;
    #pragma unroll 4
    for (int i = blockIdx.x * NTHREADS + threadIdx.x; i < TOTAL4; i += stride)
        __stcs(&o4[i], z);
}

// ---------------------------------------------------------------------------
// Phase 2: pooling. Each thread computes 2 rows' (bu, bl). Coalesced loads
// (consecutive threads -> consecutive channels), high MLP, no barriers.
// Block 0 also seeds the bias slots with the input biases.
// ---------------------------------------------------------------------------
__global__ void __launch_bounds__(NTHREADS)
pool_kernel(float* __restrict__ out,
            const float* __restrict__ u_c,
            const float* __restrict__ l_c,
            const float* __restrict__ b_out_u,
            const float* __restrict__ b_out_l) {
    if (blockIdx.x == 0 && threadIdx.x < BATCH * N_OUT) {
        out[OFF1 + threadIdx.x] = b_out_u[threadIdx.x];
        out[OFF3 + threadIdx.x] = b_out_l[threadIdx.x];
    }
    const int t0 = blockIdx.x * NTHREADS + threadIdx.x;
    #pragma unroll
    for (int k = 0; k < 2; k++) {
        const int row = t0 + k * (PGRID * NTHREADS);   // 0..262143
        const int b   = row >> 17;
        const int p   = row & (N_POOL - 1);
        const int c   = p & 127;
        const int ow  = (p >> 7) & 31;
        const int oh  = p >> 12;
        const int base = b * N_IN + oh * (2 * W * C) + ow * (2 * C) + c;

        const float u0 = u_c[base];
        const float u1 = u_c[base + C];
        const float u2 = u_c[base + W * C];
        const float u3 = u_c[base + W * C + C];
        const float l0 = l_c[base];
        const float l1 = l_c[base + C];
        const float l2 = l_c[base + W * C];
        const float l3 = l_c[base + W * C + C];

        g_bu[row] = fmaxf(fmaxf(u0, u1), fmaxf(u2, u3));
        g_bl[row] = fmaxf(fmaxf(l0, l1), fmaxf(l2, l3));
    }
}

// ---------------------------------------------------------------------------
// Phase 3: pure weight stream. Thread owns fixed (batch, o-quad); 8 static
// iterations of 2x LDG.128 (coalesced weights) + 2 L2-warm bound loads.
// No barriers until the final block reduction; 64 atomics per block.
// ---------------------------------------------------------------------------
__global__ void __launch_bounds__(NTHREADS)
reduce_kernel(float* __restrict__ out,
              const float* __restrict__ w_out_u,
              const float* __restrict__ w_out_l) {
    const int b   = blockIdx.x >> 9;                       // 512 blocks/batch
    const int tid = (blockIdx.x & 511) * NTHREADS + threadIdx.x;
    const int lane = threadIdx.x & 31;
    const int warp = threadIdx.x >> 5;
    const int oq   = threadIdx.x & 7;                      // constant per thread

    const float4* w4u = reinterpret_cast<const float4*>(w_out_u) + (size_t)b * QPB;
    const float4* w4l = reinterpret_cast<const float4*>(w_out_l) + (size_t)b * QPB;
    const float*  bup = g_bu + b * N_POOL;
    const float*  blp = g_bl + b * N_POOL;

    float4 accu = make_float4(0.f, 0.f, 0.f, 0.f);
    float4 accl = make_float4(0.f, 0.f, 0.f, 0.f);

    #pragma unroll 4
    for (int k = 0; k < 8; k++) {
        const int i   = tid + k * RSTRIDE;                 // quad index
        const int row = i >> 3;                            // local row
        const float bu = __ldg(bup + row);
        const float bl = __ldg(blp + row);
        const float4 wu = w4u[i];
        const float4 wl = w4l[i];

        accu.x += fmaxf(wu.x, 0.f) * bu + fminf(wu.x, 0.f) * bl;
        accu.y += fmaxf(wu.y, 0.f) * bu + fminf(wu.y, 0.f) * bl;
        accu.z += fmaxf(wu.z, 0.f) * bu + fminf(wu.z, 0.f) * bl;
        accu.w += fmaxf(wu.w, 0.f) * bu + fminf(wu.w, 0.f) * bl;

        accl.x += fmaxf(wl.x, 0.f) * bl + fminf(wl.x, 0.f) * bu;
        accl.y += fmaxf(wl.y, 0.f) * bl + fminf(wl.y, 0.f) * bu;
        accl.z += fmaxf(wl.z, 0.f) * bl + fminf(wl.z, 0.f) * bu;
        accl.w += fmaxf(wl.w, 0.f) * bl + fminf(wl.w, 0.f) * bu;
    }

    // warp reduction across lanes sharing the same oq (bits 3,4 of lane)
    #pragma unroll
    for (int d = 8; d < 32; d <<= 1) {
        accu.x += __shfl_xor_sync(0xFFFFFFFFu, accu.x, d);
        accu.y += __shfl_xor_sync(0xFFFFFFFFu, accu.y, d);
        accu.z += __shfl_xor_sync(0xFFFFFFFFu, accu.z, d);
        accu.w += __shfl_xor_sync(0xFFFFFFFFu, accu.w, d);
        accl.x += __shfl_xor_sync(0xFFFFFFFFu, accl.x, d);
        accl.y += __shfl_xor_sync(0xFFFFFFFFu, accl.y, d);
        accl.z += __shfl_xor_sync(0xFFFFFFFFu, accl.z, d);
        accl.w += __shfl_xor_sync(0xFFFFFFFFu, accl.w, d);
    }

    __shared__ float4 su[8][8];                            // [warp][oq]
    __shared__ float4 sl[8][8];
    if ((lane >> 3) == 0) {
        su[warp][oq] = accu;
        sl[warp][oq] = accl;
    }
    __syncthreads();

    // block reduction over the 8 warps, then 64 atomicAdds onto bias slots
    if (warp == 0) {
        const int o = lane;                                // 0..31
        const float* p = reinterpret_cast<const float*>(&su[0][0]) + (o >> 2) * 4 + (o & 3);
        float s = 0.f;
        #pragma unroll
        for (int k = 0; k < 8; k++) s += p[k * 32];
        atomicAdd(&out[OFF1 + b * N_OUT + o], s);
    } else if (warp == 1) {
        const int o = lane;
        const float* p = reinterpret_cast<const float*>(&sl[0][0]) + (o >> 2) * 4 + (o & 3);
        float s = 0.f;
        #pragma unroll
        for (int k = 0; k < 8; k++) s += p[k * 32];
        atomicAdd(&out[OFF3 + b * N_OUT + o], s);
    }
}

extern "C" void kernel_launch(void* const* d_in, const int* in_sizes, int n_in,
                              void* d_out, int out_size) {
    // metadata order: y, x_0, u_c, l_c, w_out_u, b_out_u, w_out_l, b_out_l
    const float* u_c     = (const float*)d_in[2];
    const float* l_c     = (const float*)d_in[3];
    const float* w_out_u = (const float*)d_in[4];
    const float* b_out_u = (const float*)d_in[5];
    const float* w_out_l = (const float*)d_in[6];
    const float* b_out_l = (const float*)d_in[7];
    float* out = (float*)d_out;

    zero_kernel<<<ZGRID, NTHREADS>>>(out);
    pool_kernel<<<PGRID, NTHREADS>>>(out, u_c, l_c, b_out_u, b_out_l);
    reduce_kernel<<<RGRID, NTHREADS>>>(out, w_out_u, w_out_l);
}

// round 7
// speedup vs baseline: 1.0371x; 1.0371x over previous
#include <cuda_runtime.h>

// Problem constants (fixed shapes)
#define BATCH   2
#define H       64
#define W       64
#define C       128
#define N_IN    (H * W * C)            // 524288
#define N_POOL  ((H/2) * (W/2) * C)    // 131072
#define N_OUT   32

// Output layout (concatenated, all float32):
//   [0, OFF1)       w_zero #1 : 33,554,432
//   [OFF1, OFF2)    b_out_u_  : 64
//   [OFF2, OFF3)    w_zero #2 : 33,554,432
//   [OFF3, TOTAL)   b_out_l_  : 64
#define OFF1    (BATCH * N_IN * N_OUT)         // 33554432
#define OFF2    (OFF1 + BATCH * N_OUT)         // 33554496
#define OFF3    (OFF2 + BATCH * N_IN * N_OUT)  // 67108928
#define TOTAL   (OFF3 + BATCH * N_OUT)         // 67108992

#define NTHREADS 256
#define RGRID    2048                          // one 2x2 pool window per block

// ---------------------------------------------------------------------------
// Seed the two bias slots with the input biases (runs after the memset;
// reduce_kernel's atomicAdds accumulate onto these).
// ---------------------------------------------------------------------------
__global__ void init_bias_kernel(float* __restrict__ out,
                                 const float* __restrict__ b_out_u,
                                 const float* __restrict__ b_out_l) {
    const int i = threadIdx.x;                 // 0..63
    if (i < BATCH * N_OUT) {
        out[OFF1 + i] = b_out_u[i];
        out[OFF3 + i] = b_out_l[i];
    }
}

// ---------------------------------------------------------------------------
// Fused pool + sign-split dot (R5's measured-best read kernel).
// Each block = one 2x2 pool window x 128 channels (rows r = blockIdx*128+c).
// Stage 1: coalesced pooling of u_c/l_c into smem.
// Stage 2: float4 weight streaming, warp/block reduction, 64 atomics.
// ---------------------------------------------------------------------------
__global__ void __launch_bounds__(NTHREADS)
reduce_kernel(float* __restrict__ out,
              const float* __restrict__ u_c,
              const float* __restrict__ l_c,
              const float* __restrict__ w_out_u,
              const float* __restrict__ w_out_l) {
    __shared__ float bu_s[128];
    __shared__ float bl_s[128];
    __shared__ float4 su[8][8];                // [warp][oq]
    __shared__ float4 sl[8][8];

    const int t    = threadIdx.x;
    const int bIdx = blockIdx.x;
    const int b    = bIdx >> 10;               // 1024 windows per batch
    const int widx = bIdx & 1023;
    const int oh   = widx >> 5;
    const int ow   = widx & 31;
    const int base0 = b * N_IN + oh * (2 * W * C) + ow * (2 * C);

    // ---- stage 1: cooperative coalesced pooling into smem ----
    if (t < 128) {
        const int c = t;
        const float a0 = u_c[base0 + c];
        const float a1 = u_c[base0 + C + c];
        const float a2 = u_c[base0 + W * C + c];
        const float a3 = u_c[base0 + W * C + C + c];
        bu_s[c] = fmaxf(fmaxf(a0, a1), fmaxf(a2, a3));
    } else {
        const int c = t - 128;
        const float a0 = l_c[base0 + c];
        const float a1 = l_c[base0 + C + c];
        const float a2 = l_c[base0 + W * C + c];
        const float a3 = l_c[base0 + W * C + C + c];
        bl_s[c] = fmaxf(fmaxf(a0, a1), fmaxf(a2, a3));
    }
    __syncthreads();

    // ---- stage 2: vectorized weight streaming ----
    const int warp    = t >> 5;
    const int lane    = t & 31;
    const int row_sub = lane >> 3;
    const int oq      = lane & 7;

    float4 accu = make_float4(0.f, 0.f, 0.f, 0.f);
    float4 accl = make_float4(0.f, 0.f, 0.f, 0.f);

    #pragma unroll
    for (int j = 0; j < 4; j++) {
        const int c = warp * 16 + j * 4 + row_sub;
        const int r = bIdx * 128 + c;          // global row
        const float bu = bu_s[c];
        const float bl = bl_s[c];
        const float4 wu = *reinterpret_cast<const float4*>(w_out_u + (size_t)r * N_OUT + oq * 4);
        const float4 wl = *reinterpret_cast<const float4*>(w_out_l + (size_t)r * N_OUT + oq * 4);

        accu.x += fmaxf(wu.x, 0.f) * bu + fminf(wu.x, 0.f) * bl;
        accu.y += fmaxf(wu.y, 0.f) * bu + fminf(wu.y, 0.f) * bl;
        accu.z += fmaxf(wu.z, 0.f) * bu + fminf(wu.z, 0.f) * bl;
        accu.w += fmaxf(wu.w, 0.f) * bu + fminf(wu.w, 0.f) * bl;

        accl.x += fmaxf(wl.x, 0.f) * bl + fminf(wl.x, 0.f) * bu;
        accl.y += fmaxf(wl.y, 0.f) * bl + fminf(wl.y, 0.f) * bu;
        accl.z += fmaxf(wl.z, 0.f) * bl + fminf(wl.z, 0.f) * bu;
        accl.w += fmaxf(wl.w, 0.f) * bl + fminf(wl.w, 0.f) * bu;
    }

    // reduce across row_sub (lane bits 3,4)
    #pragma unroll
    for (int d = 8; d < 32; d <<= 1) {
        accu.x += __shfl_xor_sync(0xFFFFFFFFu, accu.x, d);
        accu.y += __shfl_xor_sync(0xFFFFFFFFu, accu.y, d);
        accu.z += __shfl_xor_sync(0xFFFFFFFFu, accu.z, d);
        accu.w += __shfl_xor_sync(0xFFFFFFFFu, accu.w, d);
        accl.x += __shfl_xor_sync(0xFFFFFFFFu, accl.x, d);
        accl.y += __shfl_xor_sync(0xFFFFFFFFu, accl.y, d);
        accl.z += __shfl_xor_sync(0xFFFFFFFFu, accl.z, d);
        accl.w += __shfl_xor_sync(0xFFFFFFFFu, accl.w, d);
    }
    if (row_sub == 0) {
        su[warp][oq] = accu;
        sl[warp][oq] = accl;
    }
    __syncthreads();

    // block reduction over 8 warps, then 64 atomicAdds to bias slots
    if (warp == 0) {
        const int o = lane;
        const float* p = reinterpret_cast<const float*>(&su[0][0]) + (o >> 2) * 4 + (o & 3);
        float s = 0.f;
        #pragma unroll
        for (int k = 0; k < 8; k++) s += p[k * 32];
        atomicAdd(&out[OFF1 + b * N_OUT + o], s);
    } else if (warp == 1) {
        const int o = lane;
        const float* p = reinterpret_cast<const float*>(&sl[0][0]) + (o >> 2) * 4 + (o & 3);
        float s = 0.f;
        #pragma unroll
        for (int k = 0; k < 8; k++) s += p[k * 32];
        atomicAdd(&out[OFF3 + b * N_OUT + o], s);
    }
}

extern "C" void kernel_launch(void* const* d_in, const int* in_sizes, int n_in,
                              void* d_out, int out_size) {
    // metadata order: y, x_0, u_c, l_c, w_out_u, b_out_u, w_out_l, b_out_l
    const float* u_c     = (const float*)d_in[2];
    const float* l_c     = (const float*)d_in[3];
    const float* w_out_u = (const float*)d_in[4];
    const float* b_out_u = (const float*)d_in[5];
    const float* w_out_l = (const float*)d_in[6];
    const float* b_out_l = (const float*)d_in[7];
    float* out = (float*)d_out;

    // Phase 1: driver-optimized zero fill of the whole output (graph-capturable
    // memset node; no allocation).
    cudaMemsetAsync(out, 0, (size_t)TOTAL * sizeof(float));
    // Phase 2: seed bias slots.
    init_bias_kernel<<<1, 64>>>(out, b_out_u, b_out_l);
    // Phase 3: fused pool + sign-split reduction (atomics onto bias slots).
    reduce_kernel<<<RGRID, NTHREADS>>>(out, u_c, l_c, w_out_u, w_out_l);
}

// round 8
// speedup vs baseline: 1.0545x; 1.0168x over previous
#include <cuda_runtime.h>

// Problem constants (fixed shapes)
#define BATCH   2
#define H       64
#define W       64
#define C       128
#define N_IN    (H * W * C)            // 524288
#define N_POOL  ((H/2) * (W/2) * C)    // 131072
#define N_OUT   32

// Output layout (concatenated, all float32):
//   [0, OFF1)       w_zero #1 : 33,554,432
//   [OFF1, OFF2)    b_out_u_  : 64
//   [OFF2, OFF3)    w_zero #2 : 33,554,432
//   [OFF3, TOTAL)   b_out_l_  : 64
#define OFF1    (BATCH * N_IN * N_OUT)         // 33554432
#define OFF2    (OFF1 + BATCH * N_OUT)         // 33554496
#define OFF3    (OFF2 + BATCH * N_IN * N_OUT)  // 67108928
#define TOTAL   (OFF3 + BATCH * N_OUT)         // 67108992

#define NTHREADS 256
#define RGRID    2048                          // one 2x2 pool window per block

// ---------------------------------------------------------------------------
// Seed the two bias slots with the input biases (after the memset; the
// reduce kernel's atomicAdds accumulate onto these).
// ---------------------------------------------------------------------------
__global__ void init_bias_kernel(float* __restrict__ out,
                                 const float* __restrict__ b_out_u,
                                 const float* __restrict__ b_out_l) {
    const int i = threadIdx.x;                 // 0..63
    if (i < BATCH * N_OUT) {
        out[OFF1 + i] = b_out_u[i];
        out[OFF3 + i] = b_out_l[i];
    }
}

// ---------------------------------------------------------------------------
// Fused pool + sign-split dot, 2-FFMA-per-element form:
//   bm = (bu+bl)/2, bd = (bu-bl)/2
//   upper: max(w,0)*bu + min(w,0)*bl = w*bm + |w|*bd
//   lower: max(w,0)*bl + min(w,0)*bu = w*bm - |w|*bd
// Each block = one 2x2 pool window x 128 channels.
// ---------------------------------------------------------------------------
__global__ void __launch_bounds__(NTHREADS)
reduce_kernel(float* __restrict__ out,
              const float* __restrict__ u_c,
              const float* __restrict__ l_c,
              const float* __restrict__ w_out_u,
              const float* __restrict__ w_out_l) {
    __shared__ float bm_s[128];
    __shared__ float bd_s[128];
    __shared__ float4 su[8][8];                // [warp][oq]
    __shared__ float4 sl[8][8];

    const int t    = threadIdx.x;
    const int bIdx = blockIdx.x;
    const int b    = bIdx >> 10;               // 1024 windows per batch
    const int widx = bIdx & 1023;
    const int oh   = widx >> 5;
    const int ow   = widx & 31;
    const int base0 = b * N_IN + oh * (2 * W * C) + ow * (2 * C);

    // ---- stage 1: cooperative coalesced pooling into smem (bm, bd form) ----
    // threads 0..127 compute bu for channel t; threads 128..255 compute bl.
    __shared__ float tmp_bu[128];
    __shared__ float tmp_bl[128];
    if (t < 128) {
        const int c = t;
        const float a0 = u_c[base0 + c];
        const float a1 = u_c[base0 + C + c];
        const float a2 = u_c[base0 + W * C + c];
        const float a3 = u_c[base0 + W * C + C + c];
        tmp_bu[c] = fmaxf(fmaxf(a0, a1), fmaxf(a2, a3));
    } else {
        const int c = t - 128;
        const float a0 = l_c[base0 + c];
        const float a1 = l_c[base0 + C + c];
        const float a2 = l_c[base0 + W * C + c];
        const float a3 = l_c[base0 + W * C + C + c];
        tmp_bl[c] = fmaxf(fmaxf(a0, a1), fmaxf(a2, a3));
    }
    __syncthreads();
    if (t < 128) {
        const float bu = tmp_bu[t];
        const float bl = tmp_bl[t];
        bm_s[t] = 0.5f * (bu + bl);
        bd_s[t] = 0.5f * (bu - bl);
    }
    __syncthreads();

    // ---- stage 2: vectorized weight streaming, 2 FFMA per element ----
    const int warp    = t >> 5;
    const int lane    = t & 31;
    const int row_sub = lane >> 3;
    const int oq      = lane & 7;

    // Separate accumulators keep FFMA chains independent:
    //   accu = au1 + au2,  accl = al1 - al2  (combined after the loop)
    float4 au1 = make_float4(0.f, 0.f, 0.f, 0.f);
    float4 au2 = make_float4(0.f, 0.f, 0.f, 0.f);
    float4 al1 = make_float4(0.f, 0.f, 0.f, 0.f);
    float4 al2 = make_float4(0.f, 0.f, 0.f, 0.f);

    #pragma unroll
    for (int j = 0; j < 4; j++) {
        const int c = warp * 16 + j * 4 + row_sub;
        const int r = bIdx * 128 + c;          // global row
        const float bm = bm_s[c];
        const float bd = bd_s[c];
        const float4 wu = *reinterpret_cast<const float4*>(w_out_u + (size_t)r * N_OUT + oq * 4);
        const float4 wl = *reinterpret_cast<const float4*>(w_out_l + (size_t)r * N_OUT + oq * 4);

        au1.x += wu.x * bm;  au2.x += fabsf(wu.x) * bd;
        au1.y += wu.y * bm;  au2.y += fabsf(wu.y) * bd;
        au1.z += wu.z * bm;  au2.z += fabsf(wu.z) * bd;
        au1.w += wu.w * bm;  au2.w += fabsf(wu.w) * bd;

        al1.x += wl.x * bm;  al2.x += fabsf(wl.x) * bd;
        al1.y += wl.y * bm;  al2.y += fabsf(wl.y) * bd;
        al1.z += wl.z * bm;  al2.z += fabsf(wl.z) * bd;
        al1.w += wl.w * bm;  al2.w += fabsf(wl.w) * bd;
    }

    float4 accu = make_float4(au1.x + au2.x, au1.y + au2.y,
                              au1.z + au2.z, au1.w + au2.w);
    float4 accl = make_float4(al1.x - al2.x, al1.y - al2.y,
                              al1.z - al2.z, al1.w - al2.w);

    // reduce across row_sub (lane bits 3,4)
    #pragma unroll
    for (int d = 8; d < 32; d <<= 1) {
        accu.x += __shfl_xor_sync(0xFFFFFFFFu, accu.x, d);
        accu.y += __shfl_xor_sync(0xFFFFFFFFu, accu.y, d);
        accu.z += __shfl_xor_sync(0xFFFFFFFFu, accu.z, d);
        accu.w += __shfl_xor_sync(0xFFFFFFFFu, accu.w, d);
        accl.x += __shfl_xor_sync(0xFFFFFFFFu, accl.x, d);
        accl.y += __shfl_xor_sync(0xFFFFFFFFu, accl.y, d);
        accl.z += __shfl_xor_sync(0xFFFFFFFFu, accl.z, d);
        accl.w += __shfl_xor_sync(0xFFFFFFFFu, accl.w, d);
    }
    if (row_sub == 0) {
        su[warp][oq] = accu;
        sl[warp][oq] = accl;
    }
    __syncthreads();

    // block reduction over 8 warps, then 64 atomicAdds to bias slots
    if (warp == 0) {
        const int o = lane;
        const float* p = reinterpret_cast<const float*>(&su[0][0]) + (o >> 2) * 4 + (o & 3);
        float s = 0.f;
        #pragma unroll
        for (int k = 0; k < 8; k++) s += p[k * 32];
        atomicAdd(&out[OFF1 + b * N_OUT + o], s);
    } else if (warp == 1) {
        const int o = lane;
        const float* p = reinterpret_cast<const float*>(&sl[0][0]) + (o >> 2) * 4 + (o & 3);
        float s = 0.f;
        #pragma unroll
        for (int k = 0; k < 8; k++) s += p[k * 32];
        atomicAdd(&out[OFF3 + b * N_OUT + o], s);
    }
}

extern "C" void kernel_launch(void* const* d_in, const int* in_sizes, int n_in,
                              void* d_out, int out_size) {
    // metadata order: y, x_0, u_c, l_c, w_out_u, b_out_u, w_out_l, b_out_l
    const float* u_c     = (const float*)d_in[2];
    const float* l_c     = (const float*)d_in[3];
    const float* w_out_u = (const float*)d_in[4];
    const float* b_out_u = (const float*)d_in[5];
    const float* w_out_l = (const float*)d_in[6];
    const float* b_out_l = (const float*)d_in[7];
    float* out = (float*)d_out;

    // Phase 1: driver zero fill (at the ~5 TB/s store ceiling).
    cudaMemsetAsync(out, 0, (size_t)TOTAL * sizeof(float));
    // Phase 2: seed bias slots.
    init_bias_kernel<<<1, 64>>>(out, b_out_u, b_out_l);
    // Phase 3: fused pool + 2-FFMA sign-split reduction.
    reduce_kernel<<<RGRID, NTHREADS>>>(out, u_c, l_c, w_out_u, w_out_l);
}

// round 9
// speedup vs baseline: 1.0916x; 1.0352x over previous
#include <cuda_runtime.h>

// Problem constants (fixed shapes)
#define BATCH   2
#define H       64
#define W       64
#define C       128
#define N_IN    (H * W * C)            // 524288
#define N_POOL  ((H/2) * (W/2) * C)    // 131072
#define N_OUT   32

// Output layout (concatenated, all float32):
//   [0, OFF1)       w_zero #1 : 33,554,432
//   [OFF1, OFF2)    b_out_u_  : 64
//   [OFF2, OFF3)    w_zero #2 : 33,554,432
//   [OFF3, TOTAL)   b_out_l_  : 64
#define OFF1    (BATCH * N_IN * N_OUT)         // 33554432
#define OFF2    (OFF1 + BATCH * N_OUT)         // 33554496
#define OFF3    (OFF2 + BATCH * N_IN * N_OUT)  // 67108928
#define TOTAL   (OFF3 + BATCH * N_OUT)         // 67108992

#define NTHREADS 256
#define RGRID    2048                          // one 2x2 pool window per block

// ---------------------------------------------------------------------------
// Seed the two bias slots with the input biases (after the memset; the
// reduce kernel's atomicAdds accumulate onto these).
// ---------------------------------------------------------------------------
__global__ void init_bias_kernel(float* __restrict__ out,
                                 const float* __restrict__ b_out_u,
                                 const float* __restrict__ b_out_l) {
    const int i = threadIdx.x;                 // 0..63
    if (i < BATCH * N_OUT) {
        out[OFF1 + i] = b_out_u[i];
        out[OFF3 + i] = b_out_l[i];
    }
}

__device__ __forceinline__ float4 ldcs4(const float* p) {
    return __ldcs(reinterpret_cast<const float4*>(p));
}

// ---------------------------------------------------------------------------
// Fused pool + sign-split dot.
//   bm = (bu+bl)/2, bd = (bu-bl)/2
//   upper: w*bm + |w|*bd      lower: w*bm - |w|*bd
// Stage 2 front-batches ALL 8 LDG.128 into register buffers before any
// consumer, forcing MLP=8 per thread (latency 577/8 instead of 577/2-3).
// ---------------------------------------------------------------------------
__global__ void __launch_bounds__(NTHREADS)
reduce_kernel(float* __restrict__ out,
              const float* __restrict__ u_c,
              const float* __restrict__ l_c,
              const float* __restrict__ w_out_u,
              const float* __restrict__ w_out_l) {
    __shared__ float bm_s[128];
    __shared__ float bd_s[128];
    __shared__ float tmp_bu[128];
    __shared__ float tmp_bl[128];
    __shared__ float4 su[8][8];                // [warp][oq]
    __shared__ float4 sl[8][8];

    const int t    = threadIdx.x;
    const int bIdx = blockIdx.x;
    const int b    = bIdx >> 10;               // 1024 windows per batch
    const int widx = bIdx & 1023;
    const int oh   = widx >> 5;
    const int ow   = widx & 31;
    const int base0 = b * N_IN + oh * (2 * W * C) + ow * (2 * C);

    // ---- stage 1: cooperative coalesced pooling into smem (bm, bd form) ----
    if (t < 128) {
        const int c = t;
        const float a0 = u_c[base0 + c];
        const float a1 = u_c[base0 + C + c];
        const float a2 = u_c[base0 + W * C + c];
        const float a3 = u_c[base0 + W * C + C + c];
        tmp_bu[c] = fmaxf(fmaxf(a0, a1), fmaxf(a2, a3));
    } else {
        const int c = t - 128;
        const float a0 = l_c[base0 + c];
        const float a1 = l_c[base0 + C + c];
        const float a2 = l_c[base0 + W * C + c];
        const float a3 = l_c[base0 + W * C + C + c];
        tmp_bl[c] = fmaxf(fmaxf(a0, a1), fmaxf(a2, a3));
    }
    __syncthreads();
    if (t < 128) {
        const float bu = tmp_bu[t];
        const float bl = tmp_bl[t];
        bm_s[t] = 0.5f * (bu + bl);
        bd_s[t] = 0.5f * (bu - bl);
    }
    __syncthreads();

    // ---- stage 2: front-batched loads, then 2-FFMA math ----
    const int warp    = t >> 5;
    const int lane    = t & 31;
    const int row_sub = lane >> 3;
    const int oq      = lane & 7;

    // Load phase: 8 independent LDG.128, no consumers in between.
    float4 WU[4], WL[4];
    {
        const size_t rbase = (size_t)(bIdx * 128 + warp * 16 + row_sub) * N_OUT + oq * 4;
        #pragma unroll
        for (int j = 0; j < 4; j++)
            WU[j] = ldcs4(w_out_u + rbase + (size_t)j * 4 * N_OUT);
        #pragma unroll
        for (int j = 0; j < 4; j++)
            WL[j] = ldcs4(w_out_l + rbase + (size_t)j * 4 * N_OUT);
    }

    // Compute phase.
    float4 au1 = make_float4(0.f, 0.f, 0.f, 0.f);
    float4 au2 = make_float4(0.f, 0.f, 0.f, 0.f);
    float4 al1 = make_float4(0.f, 0.f, 0.f, 0.f);
    float4 al2 = make_float4(0.f, 0.f, 0.f, 0.f);

    #pragma unroll
    for (int j = 0; j < 4; j++) {
        const int c = warp * 16 + j * 4 + row_sub;
        const float bm = bm_s[c];
        const float bd = bd_s[c];
        const float4 wu = WU[j];
        const float4 wl = WL[j];

        au1.x += wu.x * bm;  au2.x += fabsf(wu.x) * bd;
        au1.y += wu.y * bm;  au2.y += fabsf(wu.y) * bd;
        au1.z += wu.z * bm;  au2.z += fabsf(wu.z) * bd;
        au1.w += wu.w * bm;  au2.w += fabsf(wu.w) * bd;

        al1.x += wl.x * bm;  al2.x += fabsf(wl.x) * bd;
        al1.y += wl.y * bm;  al2.y += fabsf(wl.y) * bd;
        al1.z += wl.z * bm;  al2.z += fabsf(wl.z) * bd;
        al1.w += wl.w * bm;  al2.w += fabsf(wl.w) * bd;
    }

    float4 accu = make_float4(au1.x + au2.x, au1.y + au2.y,
                              au1.z + au2.z, au1.w + au2.w);
    float4 accl = make_float4(al1.x - al2.x, al1.y - al2.y,
                              al1.z - al2.z, al1.w - al2.w);

    // reduce across row_sub (lane bits 3,4)
    #pragma unroll
    for (int d = 8; d < 32; d <<= 1) {
        accu.x += __shfl_xor_sync(0xFFFFFFFFu, accu.x, d);
        accu.y += __shfl_xor_sync(0xFFFFFFFFu, accu.y, d);
        accu.z += __shfl_xor_sync(0xFFFFFFFFu, accu.z, d);
        accu.w += __shfl_xor_sync(0xFFFFFFFFu, accu.w, d);
        accl.x += __shfl_xor_sync(0xFFFFFFFFu, accl.x, d);
        accl.y += __shfl_xor_sync(0xFFFFFFFFu, accl.y, d);
        accl.z += __shfl_xor_sync(0xFFFFFFFFu, accl.z, d);
        accl.w += __shfl_xor_sync(0xFFFFFFFFu, accl.w, d);
    }
    if (row_sub == 0) {
        su[warp][oq] = accu;
        sl[warp][oq] = accl;
    }
    __syncthreads();

    // block reduction over 8 warps, then 64 atomicAdds to bias slots
    if (warp == 0) {
        const int o = lane;
        const float* p = reinterpret_cast<const float*>(&su[0][0]) + (o >> 2) * 4 + (o & 3);
        float s = 0.f;
        #pragma unroll
        for (int k = 0; k < 8; k++) s += p[k * 32];
        atomicAdd(&out[OFF1 + b * N_OUT + o], s);
    } else if (warp == 1) {
        const int o = lane;
        const float* p = reinterpret_cast<const float*>(&sl[0][0]) + (o >> 2) * 4 + (o & 3);
        float s = 0.f;
        #pragma unroll
        for (int k = 0; k < 8; k++) s += p[k * 32];
        atomicAdd(&out[OFF3 + b * N_OUT + o], s);
    }
}

extern "C" void kernel_launch(void* const* d_in, const int* in_sizes, int n_in,
                              void* d_out, int out_size) {
    // metadata order: y, x_0, u_c, l_c, w_out_u, b_out_u, w_out_l, b_out_l
    const float* u_c     = (const float*)d_in[2];
    const float* l_c     = (const float*)d_in[3];
    const float* w_out_u = (const float*)d_in[4];
    const float* b_out_u = (const float*)d_in[5];
    const float* w_out_l = (const float*)d_in[6];
    const float* b_out_l = (const float*)d_in[7];
    float* out = (float*)d_out;

    // Phase 1: driver zero fill (at the ~5 TB/s store ceiling).
    cudaMemsetAsync(out, 0, (size_t)TOTAL * sizeof(float));
    // Phase 2: seed bias slots.
    init_bias_kernel<<<1, 64>>>(out, b_out_u, b_out_l);
    // Phase 3: fused pool + MLP-8 sign-split reduction.
    reduce_kernel<<<RGRID, NTHREADS>>>(out, u_c, l_c, w_out_u, w_out_l);
}